// round 6
// baseline (speedup 1.0000x reference)
#include <cuda_runtime.h>
#include <cuda_fp16.h>
#include <cstdint>

#define NB 2
#define NH 16
#define HD 64
#define SEQ 2048
#define HID 1024

// fp16 scratch: Q/K/V in [b, h, s, d] layout (8 MB each, static => allocation-free)
__device__ __half g_q[(size_t)NB * NH * SEQ * HD];
__device__ __half g_k[(size_t)NB * NH * SEQ * HD];
__device__ __half g_v[(size_t)NB * NH * SEQ * HD];

// fp16 copies of inputs: former[4M] | latter[4M] | Wq[1M] | Wk[1M] | Wv[1M]
#define CVT_FORMER 0
#define CVT_LATTER ((size_t)NB * SEQ * HID)
#define CVT_W      ((size_t)2 * NB * SEQ * HID)
#define CVT_TOTAL  (CVT_W + (size_t)3 * HID * HID)
__device__ __half g_cvt[CVT_TOTAL];

// ---------------------------------------------------------------------------
// PTX helpers
// ---------------------------------------------------------------------------
__device__ __forceinline__ uint32_t smem_u32(const void* p) {
    return (uint32_t)__cvta_generic_to_shared(p);
}

__device__ __forceinline__ void ldmatrix_x4(uint32_t& r0, uint32_t& r1, uint32_t& r2,
                                            uint32_t& r3, uint32_t addr) {
    asm volatile("ldmatrix.sync.aligned.m8n8.x4.shared.b16 {%0,%1,%2,%3},[%4];\n"
                 : "=r"(r0), "=r"(r1), "=r"(r2), "=r"(r3) : "r"(addr));
}

__device__ __forceinline__ void ldmatrix_x4_trans(uint32_t& r0, uint32_t& r1, uint32_t& r2,
                                                  uint32_t& r3, uint32_t addr) {
    asm volatile("ldmatrix.sync.aligned.m8n8.x4.trans.shared.b16 {%0,%1,%2,%3},[%4];\n"
                 : "=r"(r0), "=r"(r1), "=r"(r2), "=r"(r3) : "r"(addr));
}

__device__ __forceinline__ void mma16816(float* c, const uint32_t* a, const uint32_t* b) {
    asm volatile(
        "mma.sync.aligned.m16n8k16.row.col.f32.f16.f16.f32 "
        "{%0,%1,%2,%3},{%4,%5,%6,%7},{%8,%9},{%0,%1,%2,%3};\n"
        : "+f"(c[0]), "+f"(c[1]), "+f"(c[2]), "+f"(c[3])
        : "r"(a[0]), "r"(a[1]), "r"(a[2]), "r"(a[3]), "r"(b[0]), "r"(b[1]));
}

__device__ __forceinline__ uint32_t pack_half2(float x, float y) {
    __half2 h = __floats2half2_rn(x, y);
    return *(uint32_t*)&h;
}

__device__ __forceinline__ void cp_async16(uint32_t dst, const void* src) {
    asm volatile("cp.async.cg.shared.global [%0], [%1], 16;\n" ::"r"(dst), "l"(src));
}
__device__ __forceinline__ void cp_commit() {
    asm volatile("cp.async.commit_group;\n" ::: "memory");
}
__device__ __forceinline__ void cp_wait1() {
    asm volatile("cp.async.wait_group 1;\n" ::: "memory");
}
__device__ __forceinline__ void cp_wait0() {
    asm volatile("cp.async.wait_group 0;\n" ::: "memory");
}

// ---------------------------------------------------------------------------
// Convert kernel: fp32 inputs -> fp16 staging (memory-bound, ~12 us)
// ---------------------------------------------------------------------------
__global__ __launch_bounds__(256) void convert_inputs(
    const float* __restrict__ former, const float* __restrict__ latter,
    const float* __restrict__ Wq, const float* __restrict__ Wk,
    const float* __restrict__ Wv) {
    size_t i4 = ((size_t)blockIdx.x * 256 + threadIdx.x) * 4;
    if (i4 >= CVT_TOTAL) return;

    const float* src;
    size_t off;
    if (i4 < CVT_LATTER)      { src = former; off = i4; }
    else if (i4 < CVT_W)      { src = latter; off = i4 - CVT_LATTER; }
    else {
        size_t w = i4 - CVT_W;
        size_t wsz = (size_t)HID * HID;
        if (w < wsz)            { src = Wq; off = w; }
        else if (w < 2 * wsz)   { src = Wk; off = w - wsz; }
        else                    { src = Wv; off = w - 2 * wsz; }
    }
    float4 v = *(const float4*)&src[off];
    __half2* dst = (__half2*)&g_cvt[i4];
    dst[0] = __floats2half2_rn(v.x, v.y);
    dst[1] = __floats2half2_rn(v.z, v.w);
}

// ---------------------------------------------------------------------------
// QKV projection GEMM (fp16 in, fp32 accum): Y = X @ W + b, out fp16 [b,h,s,d].
// M=4096, N=1024, K=1024. CTA tile 128x128x32, 8 warps (2x4), warp tile 64x32.
// 2-stage cp.async double buffering. (unchanged from R4 — 104 us measured)
// ---------------------------------------------------------------------------
__global__ __launch_bounds__(256) void qkv_gemm(
    const float* __restrict__ bq, const float* __restrict__ bk,
    const float* __restrict__ bv) {
    const int which = blockIdx.z;
    const __half* X    = g_cvt + ((which == 0) ? CVT_FORMER : CVT_LATTER);
    const __half* W    = g_cvt + CVT_W + (size_t)which * HID * HID;
    const float* bias  = (which == 0) ? bq : (which == 1) ? bk : bv;
    __half* out        = (which == 0) ? g_q : (which == 1) ? g_k : g_v;

    __shared__ __align__(16) __half sA[2][128 * 40];
    __shared__ __align__(16) __half sB[2][32 * 136];

    const int tid = threadIdx.x;
    const int lane = tid & 31, warp = tid >> 5;
    const int wm = warp >> 2, wn = warp & 3;
    const int m0 = blockIdx.y * 128, n0 = blockIdx.x * 128;

    auto prefetch = [&](int kb, int buf) {
#pragma unroll
        for (int t = 0; t < 2; t++) {
            int i = tid + t * 256;
            int row = i >> 2, seg = i & 3;
            cp_async16(smem_u32(&sA[buf][row * 40 + seg * 8]),
                       &X[(size_t)(m0 + row) * HID + kb + seg * 8]);
        }
#pragma unroll
        for (int t = 0; t < 2; t++) {
            int i = tid + t * 256;
            int row = i >> 4, seg = i & 15;
            cp_async16(smem_u32(&sB[buf][row * 136 + seg * 8]),
                       &W[(size_t)(kb + row) * HID + n0 + seg * 8]);
        }
        cp_commit();
    };

    float c[4][4][4];
#pragma unroll
    for (int i = 0; i < 4; i++)
#pragma unroll
        for (int j = 0; j < 4; j++)
#pragma unroll
            for (int e = 0; e < 4; e++) c[i][j][e] = 0.f;

    prefetch(0, 0);

    const int NKB = HID / 32;
    for (int it = 0; it < NKB; it++) {
        const int cur = it & 1;
        if (it + 1 < NKB) {
            prefetch((it + 1) * 32, cur ^ 1);
            cp_wait1();
        } else {
            cp_wait0();
        }
        __syncthreads();

        const __half* tA = sA[cur];
        const __half* tB = sB[cur];

#pragma unroll
        for (int ks = 0; ks < 2; ks++) {
            const int k0 = ks * 16;
            uint32_t a[4][4];
#pragma unroll
            for (int im = 0; im < 4; im++) {
                int row = wm * 64 + im * 16 + (lane & 15);
                int col = k0 + (lane >> 4) * 8;
                ldmatrix_x4(a[im][0], a[im][1], a[im][2], a[im][3],
                            smem_u32(&tA[row * 40 + col]));
            }
            uint32_t bf[4][2];
#pragma unroll
            for (int jb = 0; jb < 2; jb++) {
                int nn = wn * 32 + jb * 16 + ((lane >= 16) ? 8 : 0);
                int kr = k0 + (lane & 7) + ((lane >> 3) & 1) * 8;
                uint32_t r0, r1, r2, r3;
                ldmatrix_x4_trans(r0, r1, r2, r3, smem_u32(&tB[kr * 136 + nn]));
                bf[jb * 2][0] = r0; bf[jb * 2][1] = r1;
                bf[jb * 2 + 1][0] = r2; bf[jb * 2 + 1][1] = r3;
            }
#pragma unroll
            for (int im = 0; im < 4; im++)
#pragma unroll
                for (int jn = 0; jn < 4; jn++) mma16816(c[im][jn], a[im], bf[jn]);
        }
        __syncthreads();
    }

    const int g = lane >> 2, t4 = lane & 3;
#pragma unroll
    for (int im = 0; im < 4; im++) {
#pragma unroll
        for (int jn = 0; jn < 4; jn++) {
            int row0 = m0 + wm * 64 + im * 16 + g;
            int col = n0 + wn * 32 + jn * 8 + t4 * 2;
            float b0 = bias[col], b1 = bias[col + 1];
            int bb = row0 >> 11;
            int ss = row0 & (SEQ - 1);
            int hh = col >> 6, dd = col & 63;
            size_t base = ((size_t)(bb * NH + hh) * SEQ);
            *(__half2*)&out[(base + ss) * HD + dd] =
                __floats2half2_rn(c[im][jn][0] + b0, c[im][jn][1] + b1);
            *(__half2*)&out[(base + ((row0 + 8) & (SEQ - 1))) * HD + dd] =
                __floats2half2_rn(c[im][jn][2] + b0, c[im][jn][3] + b1);
        }
    }
}

// ---------------------------------------------------------------------------
// Flash attention: 1 CTA per (bh, 64-row Q tile). 4 warps x 16 rows.
// KV tiles of 64, online softmax, fp32 accumulators, fp16 mma operands.
// Round 6: KV loop unrolled x2 (compile-time buffer index -> hoisted address
// math), deferred lane-reduction of the softmax denominator, float2 mask loads.
// ---------------------------------------------------------------------------
__global__ __launch_bounds__(128, 4) void flash_attn(const float* __restrict__ mask,
                                                     float* __restrict__ out) {
    const int bh = blockIdx.y;
    const int b = bh >> 4, h = bh & 15;
    const int q0 = blockIdx.x * 64;

    __shared__ __align__(16) __half sQ[64 * 72];
    __shared__ __align__(16) __half sK[2][64 * 72];
    __shared__ __align__(16) __half sV[2][64 * 72];
    __shared__ __align__(16) float sMask[2][64];

    const int tid = threadIdx.x, lane = tid & 31, warp = tid >> 5;
    const int g = lane >> 2, t4 = lane & 3;
    const __half* Q = g_q + (size_t)bh * SEQ * HD;
    const __half* K = g_k + (size_t)bh * SEQ * HD;
    const __half* V = g_v + (size_t)bh * SEQ * HD;
    const float* maskRow = mask + (size_t)b * SEQ;

    auto prefetch = [&](int tile, int buf) {
        const __half* Kt = K + (size_t)tile * 64 * HD;
        const __half* Vt = V + (size_t)tile * 64 * HD;
#pragma unroll
        for (int t = 0; t < 4; t++) {
            int cix = tid + t * 128;
            int row = cix >> 3, seg = cix & 7;
            cp_async16(smem_u32(&sK[buf][row * 72 + seg * 8]), &Kt[row * 64 + seg * 8]);
            cp_async16(smem_u32(&sV[buf][row * 72 + seg * 8]), &Vt[row * 64 + seg * 8]);
        }
        if (tid < 16)
            cp_async16(smem_u32(&sMask[buf][tid * 4]), &maskRow[tile * 64 + tid * 4]);
        cp_commit();
    };

    prefetch(0, 0);

    for (int i = tid; i < 64 * 8; i += 128) {
        int row = i >> 3, seg = i & 7;
        *(uint4*)&sQ[row * 72 + seg * 8] =
            *(const uint4*)&Q[(size_t)(q0 + row) * HD + seg * 8];
    }
    __syncthreads();

    const int wr0 = warp * 16;
    uint32_t aq[4][4];
#pragma unroll
    for (int kk = 0; kk < 4; kk++) {
        int row = wr0 + (lane & 15);
        int col = kk * 16 + (lane >> 4) * 8;
        ldmatrix_x4(aq[kk][0], aq[kk][1], aq[kk][2], aq[kk][3],
                    smem_u32(&sQ[row * 72 + col]));
    }

    float o[8][4];
#pragma unroll
    for (int j = 0; j < 8; j++)
#pragma unroll
        for (int e = 0; e < 4; e++) o[j][e] = 0.f;
    float mrow[2] = {-1e30f, -1e30f};
    float lp[2] = {0.f, 0.f};       // per-lane partial denominators (reduced at end)
    const float scale = 0.125f;

    const int NT = SEQ / 64;  // 32 tiles (even)
    for (int it0 = 0; it0 < NT; it0 += 2) {
#pragma unroll
        for (int u = 0; u < 2; u++) {     // cur == u at compile time
            const int it = it0 + u;
            if (it + 1 < NT) {
                prefetch(it + 1, u ^ 1);
                cp_wait1();
            } else {
                cp_wait0();
            }
            __syncthreads();

            const __half* tK = sK[u];
            const __half* tV = sV[u];
            const float* tM = sMask[u];

            // ---- S = Q K^T ----
            float sc[8][4];
#pragma unroll
            for (int j = 0; j < 8; j++)
#pragma unroll
                for (int e = 0; e < 4; e++) sc[j][e] = 0.f;

#pragma unroll
            for (int kk = 0; kk < 4; kk++) {
                uint32_t bk[8][2];
#pragma unroll
                for (int jb = 0; jb < 4; jb++) {
                    int row = jb * 16 + (lane & 7) + ((lane >= 16) ? 8 : 0);
                    int col = kk * 16 + ((lane >> 3) & 1) * 8;
                    uint32_t r0, r1, r2, r3;
                    ldmatrix_x4(r0, r1, r2, r3, smem_u32(&tK[row * 72 + col]));
                    bk[jb * 2][0] = r0; bk[jb * 2][1] = r1;
                    bk[jb * 2 + 1][0] = r2; bk[jb * 2 + 1][1] = r3;
                }
#pragma unroll
                for (int j = 0; j < 8; j++) mma16816(sc[j], aq[kk], bk[j]);
            }

            // ---- online softmax ----
            float tmax0 = -1e30f, tmax1 = -1e30f;
#pragma unroll
            for (int j = 0; j < 8; j++) {
                float2 mk = *(const float2*)&tM[j * 8 + t4 * 2];
                sc[j][0] = sc[j][0] * scale + mk.x;
                sc[j][1] = sc[j][1] * scale + mk.y;
                sc[j][2] = sc[j][2] * scale + mk.x;
                sc[j][3] = sc[j][3] * scale + mk.y;
                tmax0 = fmaxf(tmax0, fmaxf(sc[j][0], sc[j][1]));
                tmax1 = fmaxf(tmax1, fmaxf(sc[j][2], sc[j][3]));
            }
            tmax0 = fmaxf(tmax0, __shfl_xor_sync(0xffffffffu, tmax0, 1));
            tmax0 = fmaxf(tmax0, __shfl_xor_sync(0xffffffffu, tmax0, 2));
            tmax1 = fmaxf(tmax1, __shfl_xor_sync(0xffffffffu, tmax1, 1));
            tmax1 = fmaxf(tmax1, __shfl_xor_sync(0xffffffffu, tmax1, 2));

            float mnew0 = fmaxf(mrow[0], tmax0), mnew1 = fmaxf(mrow[1], tmax1);
            float alpha0 = __expf(mrow[0] - mnew0), alpha1 = __expf(mrow[1] - mnew1);
            mrow[0] = mnew0; mrow[1] = mnew1;

            float rs0 = 0.f, rs1 = 0.f;
            uint32_t ph[8][2];
#pragma unroll
            for (int j = 0; j < 8; j++) {
                float e0 = __expf(sc[j][0] - mnew0);
                float e1 = __expf(sc[j][1] - mnew0);
                float e2 = __expf(sc[j][2] - mnew1);
                float e3 = __expf(sc[j][3] - mnew1);
                rs0 += e0 + e1; rs1 += e2 + e3;
                ph[j][0] = pack_half2(e0, e1);
                ph[j][1] = pack_half2(e2, e3);
            }
            // deferred: no cross-lane reduce here, keep per-lane partials
            lp[0] = lp[0] * alpha0 + rs0;
            lp[1] = lp[1] * alpha1 + rs1;

#pragma unroll
            for (int j = 0; j < 8; j++) {
                o[j][0] *= alpha0; o[j][1] *= alpha0;
                o[j][2] *= alpha1; o[j][3] *= alpha1;
            }

            // ---- O += P V ----
#pragma unroll
            for (int kk = 0; kk < 4; kk++) {
                uint32_t ap[4] = {ph[2 * kk][0], ph[2 * kk][1],
                                  ph[2 * kk + 1][0], ph[2 * kk + 1][1]};
                uint32_t bv[8][2];
#pragma unroll
                for (int jb = 0; jb < 4; jb++) {
                    int row = kk * 16 + (lane & 7) + ((lane >> 3) & 1) * 8;
                    int col = jb * 16 + ((lane >= 16) ? 8 : 0);
                    uint32_t r0, r1, r2, r3;
                    ldmatrix_x4_trans(r0, r1, r2, r3, smem_u32(&tV[row * 72 + col]));
                    bv[jb * 2][0] = r0; bv[jb * 2][1] = r1;
                    bv[jb * 2 + 1][0] = r2; bv[jb * 2 + 1][1] = r3;
                }
#pragma unroll
                for (int j = 0; j < 8; j++) mma16816(o[j], ap, bv[j]);
            }
            __syncthreads();
        }
    }

    // ---- epilogue: final lane-reduction of denominators, normalize, store ----
    float l0 = lp[0], l1 = lp[1];
    l0 += __shfl_xor_sync(0xffffffffu, l0, 1);
    l0 += __shfl_xor_sync(0xffffffffu, l0, 2);
    l1 += __shfl_xor_sync(0xffffffffu, l1, 1);
    l1 += __shfl_xor_sync(0xffffffffu, l1, 2);
    float inv0 = 1.f / l0, inv1 = 1.f / l1;
#pragma unroll
    for (int j = 0; j < 8; j++) {
        int row0 = q0 + wr0 + g;
        int col = j * 8 + t4 * 2;
        size_t base0 = ((size_t)(b * SEQ + row0)) * HID + h * 64 + col;
        size_t base1 = ((size_t)(b * SEQ + row0 + 8)) * HID + h * 64 + col;
        *(float2*)&out[base0] = make_float2(o[j][0] * inv0, o[j][1] * inv0);
        *(float2*)&out[base1] = make_float2(o[j][2] * inv1, o[j][3] * inv1);
    }
}

// ---------------------------------------------------------------------------
extern "C" void kernel_launch(void* const* d_in, const int* in_sizes, int n_in,
                              void* d_out, int out_size) {
    const float* former = (const float*)d_in[0];
    const float* latter = (const float*)d_in[1];
    const float* mask   = (const float*)d_in[2];
    const float* Wq = (const float*)d_in[3];
    const float* bq = (const float*)d_in[4];
    const float* Wk = (const float*)d_in[5];
    const float* bk = (const float*)d_in[6];
    const float* Wv = (const float*)d_in[7];
    const float* bv = (const float*)d_in[8];

    size_t cvt_blocks = (CVT_TOTAL / 4 + 255) / 256;
    convert_inputs<<<(unsigned)cvt_blocks, 256>>>(former, latter, Wq, Wk, Wv);

    dim3 g1(HID / 128, (NB * SEQ) / 128, 3);
    qkv_gemm<<<g1, 256>>>(bq, bk, bv);

    dim3 g2(SEQ / 64, NB * NH);
    flash_attn<<<g2, 128>>>(mask, (float*)d_out);
}

// round 9
// speedup vs baseline: 1.0174x; 1.0174x over previous
#include <cuda_runtime.h>
#include <cuda_fp16.h>
#include <cstdint>

#define NB 2
#define NH 16
#define HD 64
#define SEQ 2048
#define HID 1024

// fp16 scratch: Q/K/V in [b, h, s, d] layout (8 MB each, static => allocation-free)
__device__ __half g_q[(size_t)NB * NH * SEQ * HD];
__device__ __half g_k[(size_t)NB * NH * SEQ * HD];
__device__ __half g_v[(size_t)NB * NH * SEQ * HD];

// fp16 copies of inputs: former[4M] | latter[4M] | Wq[1M] | Wk[1M] | Wv[1M]
#define CVT_FORMER 0
#define CVT_LATTER ((size_t)NB * SEQ * HID)
#define CVT_W      ((size_t)2 * NB * SEQ * HID)
#define CVT_TOTAL  (CVT_W + (size_t)3 * HID * HID)
__device__ __half g_cvt[CVT_TOTAL];

// mask pre-scaled by log2(e) (log2-domain softmax)
__device__ float g_maskl2[(size_t)NB * SEQ];

#define LOG2E 1.44269504088896340736f

// ---------------------------------------------------------------------------
// PTX helpers
// ---------------------------------------------------------------------------
__device__ __forceinline__ uint32_t smem_u32(const void* p) {
    return (uint32_t)__cvta_generic_to_shared(p);
}

__device__ __forceinline__ void ldmatrix_x4(uint32_t& r0, uint32_t& r1, uint32_t& r2,
                                            uint32_t& r3, uint32_t addr) {
    asm volatile("ldmatrix.sync.aligned.m8n8.x4.shared.b16 {%0,%1,%2,%3},[%4];\n"
                 : "=r"(r0), "=r"(r1), "=r"(r2), "=r"(r3) : "r"(addr));
}

__device__ __forceinline__ void ldmatrix_x4_trans(uint32_t& r0, uint32_t& r1, uint32_t& r2,
                                                  uint32_t& r3, uint32_t addr) {
    asm volatile("ldmatrix.sync.aligned.m8n8.x4.trans.shared.b16 {%0,%1,%2,%3},[%4];\n"
                 : "=r"(r0), "=r"(r1), "=r"(r2), "=r"(r3) : "r"(addr));
}

__device__ __forceinline__ void mma16816(float* c, const uint32_t* a, const uint32_t* b) {
    asm volatile(
        "mma.sync.aligned.m16n8k16.row.col.f32.f16.f16.f32 "
        "{%0,%1,%2,%3},{%4,%5,%6,%7},{%8,%9},{%0,%1,%2,%3};\n"
        : "+f"(c[0]), "+f"(c[1]), "+f"(c[2]), "+f"(c[3])
        : "r"(a[0]), "r"(a[1]), "r"(a[2]), "r"(a[3]), "r"(b[0]), "r"(b[1]));
}

__device__ __forceinline__ uint32_t pack_half2(float x, float y) {
    __half2 h = __floats2half2_rn(x, y);
    return *(uint32_t*)&h;
}

// ex2 on packed half2 (one MUFU for two elements)
__device__ __forceinline__ uint32_t ex2_h2(uint32_t x) {
    uint32_t r;
    asm("ex2.approx.f16x2 %0, %1;" : "=r"(r) : "r"(x));
    return r;
}

__device__ __forceinline__ uint32_t hadd2u(uint32_t a, uint32_t b) {
    uint32_t r;
    asm("add.f16x2 %0, %1, %2;" : "=r"(r) : "r"(a), "r"(b));
    return r;
}

__device__ __forceinline__ void cp_async16(uint32_t dst, const void* src) {
    asm volatile("cp.async.cg.shared.global [%0], [%1], 16;\n" ::"r"(dst), "l"(src));
}
__device__ __forceinline__ void cp_commit() {
    asm volatile("cp.async.commit_group;\n" ::: "memory");
}
__device__ __forceinline__ void cp_wait1() {
    asm volatile("cp.async.wait_group 1;\n" ::: "memory");
}
__device__ __forceinline__ void cp_wait0() {
    asm volatile("cp.async.wait_group 0;\n" ::: "memory");
}

// ---------------------------------------------------------------------------
// Convert kernel: fp32 inputs -> fp16 staging (memory-bound, ~12 us)
// ---------------------------------------------------------------------------
__global__ __launch_bounds__(256) void convert_inputs(
    const float* __restrict__ former, const float* __restrict__ latter,
    const float* __restrict__ Wq, const float* __restrict__ Wk,
    const float* __restrict__ Wv) {
    size_t i4 = ((size_t)blockIdx.x * 256 + threadIdx.x) * 4;
    if (i4 >= CVT_TOTAL) return;

    const float* src;
    size_t off;
    if (i4 < CVT_LATTER)      { src = former; off = i4; }
    else if (i4 < CVT_W)      { src = latter; off = i4 - CVT_LATTER; }
    else {
        size_t w = i4 - CVT_W;
        size_t wsz = (size_t)HID * HID;
        if (w < wsz)            { src = Wq; off = w; }
        else if (w < 2 * wsz)   { src = Wk; off = w - wsz; }
        else                    { src = Wv; off = w - 2 * wsz; }
    }
    float4 v = *(const float4*)&src[off];
    __half2* dst = (__half2*)&g_cvt[i4];
    dst[0] = __floats2half2_rn(v.x, v.y);
    dst[1] = __floats2half2_rn(v.z, v.w);
}

// mask * log2e  (4096 elements)
__global__ __launch_bounds__(256) void scale_mask(const float* __restrict__ mask) {
    int i = blockIdx.x * 256 + threadIdx.x;
    if (i < NB * SEQ) g_maskl2[i] = mask[i] * LOG2E;
}

// ---------------------------------------------------------------------------
// QKV projection GEMM (fp16 in, fp32 accum): Y = X @ W + b, out fp16 [b,h,s,d].
// M=4096, N=1024, K=1024. CTA tile 128x128x32, 8 warps (2x4), warp tile 64x32.
// 2-stage cp.async double buffering. (proven R4 config — 104 us measured)
// ---------------------------------------------------------------------------
__global__ __launch_bounds__(256) void qkv_gemm(
    const float* __restrict__ bq, const float* __restrict__ bk,
    const float* __restrict__ bv) {
    const int which = blockIdx.z;
    const __half* X    = g_cvt + ((which == 0) ? CVT_FORMER : CVT_LATTER);
    const __half* W    = g_cvt + CVT_W + (size_t)which * HID * HID;
    const float* bias  = (which == 0) ? bq : (which == 1) ? bk : bv;
    __half* out        = (which == 0) ? g_q : (which == 1) ? g_k : g_v;

    __shared__ __align__(16) __half sA[2][128 * 40];
    __shared__ __align__(16) __half sB[2][32 * 136];

    const int tid = threadIdx.x;
    const int lane = tid & 31, warp = tid >> 5;
    const int wm = warp >> 2, wn = warp & 3;
    const int m0 = blockIdx.y * 128, n0 = blockIdx.x * 128;

    auto prefetch = [&](int kb, int buf) {
#pragma unroll
        for (int t = 0; t < 2; t++) {
            int i = tid + t * 256;
            int row = i >> 2, seg = i & 3;
            cp_async16(smem_u32(&sA[buf][row * 40 + seg * 8]),
                       &X[(size_t)(m0 + row) * HID + kb + seg * 8]);
        }
#pragma unroll
        for (int t = 0; t < 2; t++) {
            int i = tid + t * 256;
            int row = i >> 4, seg = i & 15;
            cp_async16(smem_u32(&sB[buf][row * 136 + seg * 8]),
                       &W[(size_t)(kb + row) * HID + n0 + seg * 8]);
        }
        cp_commit();
    };

    float c[4][4][4];
#pragma unroll
    for (int i = 0; i < 4; i++)
#pragma unroll
        for (int j = 0; j < 4; j++)
#pragma unroll
            for (int e = 0; e < 4; e++) c[i][j][e] = 0.f;

    prefetch(0, 0);

    const int NKB = HID / 32;
    for (int it = 0; it < NKB; it++) {
        const int cur = it & 1;
        if (it + 1 < NKB) {
            prefetch((it + 1) * 32, cur ^ 1);
            cp_wait1();
        } else {
            cp_wait0();
        }
        __syncthreads();

        const __half* tA = sA[cur];
        const __half* tB = sB[cur];

#pragma unroll
        for (int ks = 0; ks < 2; ks++) {
            const int k0 = ks * 16;
            uint32_t a[4][4];
#pragma unroll
            for (int im = 0; im < 4; im++) {
                int row = wm * 64 + im * 16 + (lane & 15);
                int col = k0 + (lane >> 4) * 8;
                ldmatrix_x4(a[im][0], a[im][1], a[im][2], a[im][3],
                            smem_u32(&tA[row * 40 + col]));
            }
            uint32_t bf[4][2];
#pragma unroll
            for (int jb = 0; jb < 2; jb++) {
                int nn = wn * 32 + jb * 16 + ((lane >= 16) ? 8 : 0);
                int kr = k0 + (lane & 7) + ((lane >> 3) & 1) * 8;
                uint32_t r0, r1, r2, r3;
                ldmatrix_x4_trans(r0, r1, r2, r3, smem_u32(&tB[kr * 136 + nn]));
                bf[jb * 2][0] = r0; bf[jb * 2][1] = r1;
                bf[jb * 2 + 1][0] = r2; bf[jb * 2 + 1][1] = r3;
            }
#pragma unroll
            for (int im = 0; im < 4; im++)
#pragma unroll
                for (int jn = 0; jn < 4; jn++) mma16816(c[im][jn], a[im], bf[jn]);
        }
        __syncthreads();
    }

    const int g = lane >> 2, t4 = lane & 3;
#pragma unroll
    for (int im = 0; im < 4; im++) {
#pragma unroll
        for (int jn = 0; jn < 4; jn++) {
            int row0 = m0 + wm * 64 + im * 16 + g;
            int col = n0 + wn * 32 + jn * 8 + t4 * 2;
            float b0 = bias[col], b1 = bias[col + 1];
            int bb = row0 >> 11;
            int ss = row0 & (SEQ - 1);
            int hh = col >> 6, dd = col & 63;
            size_t base = ((size_t)(bb * NH + hh) * SEQ);
            *(__half2*)&out[(base + ss) * HD + dd] =
                __floats2half2_rn(c[im][jn][0] + b0, c[im][jn][1] + b1);
            *(__half2*)&out[(base + ((row0 + 8) & (SEQ - 1))) * HD + dd] =
                __floats2half2_rn(c[im][jn][2] + b0, c[im][jn][3] + b1);
        }
    }
}

// ---------------------------------------------------------------------------
// Flash attention: 1 CTA per (bh, 64-row Q tile). 4 warps x 16 rows.
// KV tiles of 64, online softmax in LOG2 domain, fp32 accumulators.
// exp2-based softmax, f16x2 EX2 (half the MUFU), HADD2 row sums.
// ---------------------------------------------------------------------------
__global__ __launch_bounds__(128, 4) void flash_attn(float* __restrict__ out) {
    const int bh = blockIdx.y;
    const int b = bh >> 4, h = bh & 15;
    const int q0 = blockIdx.x * 64;

    __shared__ __align__(16) __half sQ[64 * 72];
    __shared__ __align__(16) __half sK[2][64 * 72];
    __shared__ __align__(16) __half sV[2][64 * 72];
    __shared__ __align__(16) float sMask[2][64];

    const int tid = threadIdx.x, lane = tid & 31, warp = tid >> 5;
    const int g = lane >> 2, t4 = lane & 3;
    const __half* Q = g_q + (size_t)bh * SEQ * HD;
    const __half* K = g_k + (size_t)bh * SEQ * HD;
    const __half* V = g_v + (size_t)bh * SEQ * HD;
    const float* maskRow = g_maskl2 + (size_t)b * SEQ;

    auto prefetch = [&](int tile, int buf) {
        const __half* Kt = K + (size_t)tile * 64 * HD;
        const __half* Vt = V + (size_t)tile * 64 * HD;
#pragma unroll
        for (int t = 0; t < 4; t++) {
            int cix = tid + t * 128;
            int row = cix >> 3, seg = cix & 7;
            cp_async16(smem_u32(&sK[buf][row * 72 + seg * 8]), &Kt[row * 64 + seg * 8]);
            cp_async16(smem_u32(&sV[buf][row * 72 + seg * 8]), &Vt[row * 64 + seg * 8]);
        }
        if (tid < 16)
            cp_async16(smem_u32(&sMask[buf][tid * 4]), &maskRow[tile * 64 + tid * 4]);
        cp_commit();
    };

    prefetch(0, 0);

    for (int i = tid; i < 64 * 8; i += 128) {
        int row = i >> 3, seg = i & 7;
        *(uint4*)&sQ[row * 72 + seg * 8] =
            *(const uint4*)&Q[(size_t)(q0 + row) * HD + seg * 8];
    }
    __syncthreads();

    const int wr0 = warp * 16;
    uint32_t aq[4][4];
#pragma unroll
    for (int kk = 0; kk < 4; kk++) {
        int row = wr0 + (lane & 15);
        int col = kk * 16 + (lane >> 4) * 8;
        ldmatrix_x4(aq[kk][0], aq[kk][1], aq[kk][2], aq[kk][3],
                    smem_u32(&sQ[row * 72 + col]));
    }

    float o[8][4];
#pragma unroll
    for (int j = 0; j < 8; j++)
#pragma unroll
        for (int e = 0; e < 4; e++) o[j][e] = 0.f;
    float mrow[2] = {-1e30f, -1e30f};   // log2-domain running max
    float lp[2] = {0.f, 0.f};           // per-lane partial denominators
    const float scale2 = 0.125f * LOG2E;  // fold log2e into the QK scale

    const int NT = SEQ / 64;
    for (int it0 = 0; it0 < NT; it0 += 2) {
#pragma unroll
        for (int u = 0; u < 2; u++) {
            const int it = it0 + u;
            if (it + 1 < NT) {
                prefetch(it + 1, u ^ 1);
                cp_wait1();
            } else {
                cp_wait0();
            }
            __syncthreads();

            const __half* tK = sK[u];
            const __half* tV = sV[u];
            const float* tM = sMask[u];

            // ---- S = Q K^T (log2 domain after scaling) ----
            float sc[8][4];
#pragma unroll
            for (int j = 0; j < 8; j++)
#pragma unroll
                for (int e = 0; e < 4; e++) sc[j][e] = 0.f;

#pragma unroll
            for (int kk = 0; kk < 4; kk++) {
                uint32_t bk[8][2];
#pragma unroll
                for (int jb = 0; jb < 4; jb++) {
                    int row = jb * 16 + (lane & 7) + ((lane >= 16) ? 8 : 0);
                    int col = kk * 16 + ((lane >> 3) & 1) * 8;
                    uint32_t r0, r1, r2, r3;
                    ldmatrix_x4(r0, r1, r2, r3, smem_u32(&tK[row * 72 + col]));
                    bk[jb * 2][0] = r0; bk[jb * 2][1] = r1;
                    bk[jb * 2 + 1][0] = r2; bk[jb * 2 + 1][1] = r3;
                }
#pragma unroll
                for (int j = 0; j < 8; j++) mma16816(sc[j], aq[kk], bk[j]);
            }

            // ---- online softmax (base-2) ----
            float tmax0 = -1e30f, tmax1 = -1e30f;
#pragma unroll
            for (int j = 0; j < 8; j++) {
                float2 mk = *(const float2*)&tM[j * 8 + t4 * 2];
                sc[j][0] = sc[j][0] * scale2 + mk.x;
                sc[j][1] = sc[j][1] * scale2 + mk.y;
                sc[j][2] = sc[j][2] * scale2 + mk.x;
                sc[j][3] = sc[j][3] * scale2 + mk.y;
                tmax0 = fmaxf(tmax0, fmaxf(sc[j][0], sc[j][1]));
                tmax1 = fmaxf(tmax1, fmaxf(sc[j][2], sc[j][3]));
            }
            tmax0 = fmaxf(tmax0, __shfl_xor_sync(0xffffffffu, tmax0, 1));
            tmax0 = fmaxf(tmax0, __shfl_xor_sync(0xffffffffu, tmax0, 2));
            tmax1 = fmaxf(tmax1, __shfl_xor_sync(0xffffffffu, tmax1, 1));
            tmax1 = fmaxf(tmax1, __shfl_xor_sync(0xffffffffu, tmax1, 2));

            float mnew0 = fmaxf(mrow[0], tmax0), mnew1 = fmaxf(mrow[1], tmax1);
            float alpha0 = exp2f(mrow[0] - mnew0), alpha1 = exp2f(mrow[1] - mnew1);
            mrow[0] = mnew0; mrow[1] = mnew1;

            // P = 2^(sc - m): pack fp32 diffs to half2, one EX2 per pair
            uint32_t ph[8][2];
            uint32_t racc0 = 0, racc1 = 0;   // half2 zero
#pragma unroll
            for (int j = 0; j < 8; j++) {
                uint32_t p01 = ex2_h2(pack_half2(sc[j][0] - mnew0, sc[j][1] - mnew0));
                uint32_t p23 = ex2_h2(pack_half2(sc[j][2] - mnew1, sc[j][3] - mnew1));
                ph[j][0] = p01; ph[j][1] = p23;
                racc0 = hadd2u(racc0, p01);
                racc1 = hadd2u(racc1, p23);
            }
            float2 r0 = __half22float2(*(__half2*)&racc0);
            float2 r1 = __half22float2(*(__half2*)&racc1);
            lp[0] = lp[0] * alpha0 + (r0.x + r0.y);
            lp[1] = lp[1] * alpha1 + (r1.x + r1.y);

#pragma unroll
            for (int j = 0; j < 8; j++) {
                o[j][0] *= alpha0; o[j][1] *= alpha0;
                o[j][2] *= alpha1; o[j][3] *= alpha1;
            }

            // ---- O += P V ----
#pragma unroll
            for (int kk = 0; kk < 4; kk++) {
                uint32_t ap[4] = {ph[2 * kk][0], ph[2 * kk][1],
                                  ph[2 * kk + 1][0], ph[2 * kk + 1][1]};
                uint32_t bv[8][2];
#pragma unroll
                for (int jb = 0; jb < 4; jb++) {
                    int row = kk * 16 + (lane & 7) + ((lane >> 3) & 1) * 8;
                    int col = jb * 16 + ((lane >= 16) ? 8 : 0);
                    uint32_t r2, r3, r4, r5;
                    ldmatrix_x4_trans(r2, r3, r4, r5, smem_u32(&tV[row * 72 + col]));
                    bv[jb * 2][0] = r2; bv[jb * 2][1] = r3;
                    bv[jb * 2 + 1][0] = r4; bv[jb * 2 + 1][1] = r5;
                }
#pragma unroll
                for (int j = 0; j < 8; j++) mma16816(o[j], ap, bv[j]);
            }
            __syncthreads();
        }
    }

    // ---- epilogue: lane-reduce denominators, normalize, store ----
    float l0 = lp[0], l1 = lp[1];
    l0 += __shfl_xor_sync(0xffffffffu, l0, 1);
    l0 += __shfl_xor_sync(0xffffffffu, l0, 2);
    l1 += __shfl_xor_sync(0xffffffffu, l1, 1);
    l1 += __shfl_xor_sync(0xffffffffu, l1, 2);
    float inv0 = 1.f / l0, inv1 = 1.f / l1;
#pragma unroll
    for (int j = 0; j < 8; j++) {
        int row0 = q0 + wr0 + g;
        int col = j * 8 + t4 * 2;
        size_t base0 = ((size_t)(b * SEQ + row0)) * HID + h * 64 + col;
        size_t base1 = ((size_t)(b * SEQ + row0 + 8)) * HID + h * 64 + col;
        *(float2*)&out[base0] = make_float2(o[j][0] * inv0, o[j][1] * inv0);
        *(float2*)&out[base1] = make_float2(o[j][2] * inv1, o[j][3] * inv1);
    }
}

// ---------------------------------------------------------------------------
extern "C" void kernel_launch(void* const* d_in, const int* in_sizes, int n_in,
                              void* d_out, int out_size) {
    const float* former = (const float*)d_in[0];
    const float* latter = (const float*)d_in[1];
    const float* mask   = (const float*)d_in[2];
    const float* Wq = (const float*)d_in[3];
    const float* bq = (const float*)d_in[4];
    const float* Wk = (const float*)d_in[5];
    const float* bk = (const float*)d_in[6];
    const float* Wv = (const float*)d_in[7];
    const float* bv = (const float*)d_in[8];

    size_t cvt_blocks = (CVT_TOTAL / 4 + 255) / 256;
    convert_inputs<<<(unsigned)cvt_blocks, 256>>>(former, latter, Wq, Wk, Wv);
    scale_mask<<<(NB * SEQ + 255) / 256, 256>>>(mask);

    dim3 g1(HID / 128, (NB * SEQ) / 128, 3);
    qkv_gemm<<<g1, 256>>>(bq, bk, bv);

    dim3 g2(SEQ / 64, NB * NH);
    flash_attn<<<g2, 128>>>((float*)d_out);
}

// round 10
// speedup vs baseline: 1.0249x; 1.0074x over previous
#include <cuda_runtime.h>
#include <cuda_fp16.h>
#include <cstdint>

#define NB 2
#define NH 16
#define HD 64
#define SEQ 2048
#define HID 1024

// fp16 scratch: Q/K/V in [b, h, s, d] layout (8 MB each, static => allocation-free)
__device__ __half g_q[(size_t)NB * NH * SEQ * HD];
__device__ __half g_k[(size_t)NB * NH * SEQ * HD];
__device__ __half g_v[(size_t)NB * NH * SEQ * HD];

// fp16 copies of inputs: former[4M] | latter[4M] | Wq[1M] | Wk[1M] | Wv[1M]
#define CVT_FORMER 0
#define CVT_LATTER ((size_t)NB * SEQ * HID)
#define CVT_W      ((size_t)2 * NB * SEQ * HID)
#define CVT_TOTAL  (CVT_W + (size_t)3 * HID * HID)
__device__ __half g_cvt[CVT_TOTAL];

// mask pre-scaled by log2(e) (log2-domain softmax)
__device__ float g_maskl2[(size_t)NB * SEQ];

#define LOG2E 1.44269504088896340736f

// ---------------------------------------------------------------------------
// PTX helpers
// ---------------------------------------------------------------------------
__device__ __forceinline__ uint32_t smem_u32(const void* p) {
    return (uint32_t)__cvta_generic_to_shared(p);
}

__device__ __forceinline__ void ldmatrix_x4(uint32_t& r0, uint32_t& r1, uint32_t& r2,
                                            uint32_t& r3, uint32_t addr) {
    asm volatile("ldmatrix.sync.aligned.m8n8.x4.shared.b16 {%0,%1,%2,%3},[%4];\n"
                 : "=r"(r0), "=r"(r1), "=r"(r2), "=r"(r3) : "r"(addr));
}

__device__ __forceinline__ void ldmatrix_x4_trans(uint32_t& r0, uint32_t& r1, uint32_t& r2,
                                                  uint32_t& r3, uint32_t addr) {
    asm volatile("ldmatrix.sync.aligned.m8n8.x4.trans.shared.b16 {%0,%1,%2,%3},[%4];\n"
                 : "=r"(r0), "=r"(r1), "=r"(r2), "=r"(r3) : "r"(addr));
}

// fp32-accumulate mma (GEMM + PV)
__device__ __forceinline__ void mma16816(float* c, const uint32_t* a, const uint32_t* b) {
    asm volatile(
        "mma.sync.aligned.m16n8k16.row.col.f32.f16.f16.f32 "
        "{%0,%1,%2,%3},{%4,%5,%6,%7},{%8,%9},{%0,%1,%2,%3};\n"
        : "+f"(c[0]), "+f"(c[1]), "+f"(c[2]), "+f"(c[3])
        : "r"(a[0]), "r"(a[1]), "r"(a[2]), "r"(a[3]), "r"(b[0]), "r"(b[1]));
}

// fp16-accumulate mma (flash S = QK^T; K depth only 64 so fp16 accum is safe)
__device__ __forceinline__ void mma16816_f16(uint32_t* d, const uint32_t* a,
                                             const uint32_t* b) {
    asm volatile(
        "mma.sync.aligned.m16n8k16.row.col.f16.f16.f16.f16 "
        "{%0,%1},{%2,%3,%4,%5},{%6,%7},{%0,%1};\n"
        : "+r"(d[0]), "+r"(d[1])
        : "r"(a[0]), "r"(a[1]), "r"(a[2]), "r"(a[3]), "r"(b[0]), "r"(b[1]));
}

__device__ __forceinline__ uint32_t pack_half2(float x, float y) {
    __half2 h = __floats2half2_rn(x, y);
    return *(uint32_t*)&h;
}

// ex2 on packed half2 (one MUFU for two elements)
__device__ __forceinline__ uint32_t ex2_h2(uint32_t x) {
    uint32_t r;
    asm("ex2.approx.f16x2 %0, %1;" : "=r"(r) : "r"(x));
    return r;
}

__device__ __forceinline__ uint32_t hadd2u(uint32_t a, uint32_t b) {
    uint32_t r;
    asm("add.f16x2 %0, %1, %2;" : "=r"(r) : "r"(a), "r"(b));
    return r;
}

__device__ __forceinline__ void cp_async16(uint32_t dst, const void* src) {
    asm volatile("cp.async.cg.shared.global [%0], [%1], 16;\n" ::"r"(dst), "l"(src));
}
__device__ __forceinline__ void cp_commit() {
    asm volatile("cp.async.commit_group;\n" ::: "memory");
}
__device__ __forceinline__ void cp_wait1() {
    asm volatile("cp.async.wait_group 1;\n" ::: "memory");
}
__device__ __forceinline__ void cp_wait0() {
    asm volatile("cp.async.wait_group 0;\n" ::: "memory");
}

// ---------------------------------------------------------------------------
// Convert kernel: fp32 inputs -> fp16 staging (memory-bound, ~12 us)
// ---------------------------------------------------------------------------
__global__ __launch_bounds__(256) void convert_inputs(
    const float* __restrict__ former, const float* __restrict__ latter,
    const float* __restrict__ Wq, const float* __restrict__ Wk,
    const float* __restrict__ Wv) {
    size_t i4 = ((size_t)blockIdx.x * 256 + threadIdx.x) * 4;
    if (i4 >= CVT_TOTAL) return;

    const float* src;
    size_t off;
    if (i4 < CVT_LATTER)      { src = former; off = i4; }
    else if (i4 < CVT_W)      { src = latter; off = i4 - CVT_LATTER; }
    else {
        size_t w = i4 - CVT_W;
        size_t wsz = (size_t)HID * HID;
        if (w < wsz)            { src = Wq; off = w; }
        else if (w < 2 * wsz)   { src = Wk; off = w - wsz; }
        else                    { src = Wv; off = w - 2 * wsz; }
    }
    float4 v = *(const float4*)&src[off];
    __half2* dst = (__half2*)&g_cvt[i4];
    dst[0] = __floats2half2_rn(v.x, v.y);
    dst[1] = __floats2half2_rn(v.z, v.w);
}

// mask * log2e  (4096 elements)
__global__ __launch_bounds__(256) void scale_mask(const float* __restrict__ mask) {
    int i = blockIdx.x * 256 + threadIdx.x;
    if (i < NB * SEQ) g_maskl2[i] = mask[i] * LOG2E;
}

// ---------------------------------------------------------------------------
// QKV projection GEMM (fp16 in, fp32 accum): Y = X @ W + b, out fp16 [b,h,s,d].
// M=4096, N=1024, K=1024. CTA tile 128x128x32, 8 warps (2x4), warp tile 64x32.
// 2-stage cp.async double buffering. (proven config — 104 us measured;
// fp32 accum REQUIRED here: K=1024 makes fp16 accum error ~1e-2)
// ---------------------------------------------------------------------------
__global__ __launch_bounds__(256) void qkv_gemm(
    const float* __restrict__ bq, const float* __restrict__ bk,
    const float* __restrict__ bv) {
    const int which = blockIdx.z;
    const __half* X    = g_cvt + ((which == 0) ? CVT_FORMER : CVT_LATTER);
    const __half* W    = g_cvt + CVT_W + (size_t)which * HID * HID;
    const float* bias  = (which == 0) ? bq : (which == 1) ? bk : bv;
    __half* out        = (which == 0) ? g_q : (which == 1) ? g_k : g_v;

    __shared__ __align__(16) __half sA[2][128 * 40];
    __shared__ __align__(16) __half sB[2][32 * 136];

    const int tid = threadIdx.x;
    const int lane = tid & 31, warp = tid >> 5;
    const int wm = warp >> 2, wn = warp & 3;
    const int m0 = blockIdx.y * 128, n0 = blockIdx.x * 128;

    auto prefetch = [&](int kb, int buf) {
#pragma unroll
        for (int t = 0; t < 2; t++) {
            int i = tid + t * 256;
            int row = i >> 2, seg = i & 3;
            cp_async16(smem_u32(&sA[buf][row * 40 + seg * 8]),
                       &X[(size_t)(m0 + row) * HID + kb + seg * 8]);
        }
#pragma unroll
        for (int t = 0; t < 2; t++) {
            int i = tid + t * 256;
            int row = i >> 4, seg = i & 15;
            cp_async16(smem_u32(&sB[buf][row * 136 + seg * 8]),
                       &W[(size_t)(kb + row) * HID + n0 + seg * 8]);
        }
        cp_commit();
    };

    float c[4][4][4];
#pragma unroll
    for (int i = 0; i < 4; i++)
#pragma unroll
        for (int j = 0; j < 4; j++)
#pragma unroll
            for (int e = 0; e < 4; e++) c[i][j][e] = 0.f;

    prefetch(0, 0);

    const int NKB = HID / 32;
    for (int it = 0; it < NKB; it++) {
        const int cur = it & 1;
        if (it + 1 < NKB) {
            prefetch((it + 1) * 32, cur ^ 1);
            cp_wait1();
        } else {
            cp_wait0();
        }
        __syncthreads();

        const __half* tA = sA[cur];
        const __half* tB = sB[cur];

#pragma unroll
        for (int ks = 0; ks < 2; ks++) {
            const int k0 = ks * 16;
            uint32_t a[4][4];
#pragma unroll
            for (int im = 0; im < 4; im++) {
                int row = wm * 64 + im * 16 + (lane & 15);
                int col = k0 + (lane >> 4) * 8;
                ldmatrix_x4(a[im][0], a[im][1], a[im][2], a[im][3],
                            smem_u32(&tA[row * 40 + col]));
            }
            uint32_t bf[4][2];
#pragma unroll
            for (int jb = 0; jb < 2; jb++) {
                int nn = wn * 32 + jb * 16 + ((lane >= 16) ? 8 : 0);
                int kr = k0 + (lane & 7) + ((lane >> 3) & 1) * 8;
                uint32_t r0, r1, r2, r3;
                ldmatrix_x4_trans(r0, r1, r2, r3, smem_u32(&tB[kr * 136 + nn]));
                bf[jb * 2][0] = r0; bf[jb * 2][1] = r1;
                bf[jb * 2 + 1][0] = r2; bf[jb * 2 + 1][1] = r3;
            }
#pragma unroll
            for (int im = 0; im < 4; im++)
#pragma unroll
                for (int jn = 0; jn < 4; jn++) mma16816(c[im][jn], a[im], bf[jn]);
        }
        __syncthreads();
    }

    const int g = lane >> 2, t4 = lane & 3;
#pragma unroll
    for (int im = 0; im < 4; im++) {
#pragma unroll
        for (int jn = 0; jn < 4; jn++) {
            int row0 = m0 + wm * 64 + im * 16 + g;
            int col = n0 + wn * 32 + jn * 8 + t4 * 2;
            float b0 = bias[col], b1 = bias[col + 1];
            int bb = row0 >> 11;
            int ss = row0 & (SEQ - 1);
            int hh = col >> 6, dd = col & 63;
            size_t base = ((size_t)(bb * NH + hh) * SEQ);
            *(__half2*)&out[(base + ss) * HD + dd] =
                __floats2half2_rn(c[im][jn][0] + b0, c[im][jn][1] + b1);
            *(__half2*)&out[(base + ((row0 + 8) & (SEQ - 1))) * HD + dd] =
                __floats2half2_rn(c[im][jn][2] + b0, c[im][jn][3] + b1);
        }
    }
}

// ---------------------------------------------------------------------------
// Flash attention: 1 CTA per (bh, 64-row Q tile). 4 warps x 16 rows.
// KV tiles of 64, online softmax in LOG2 domain.
// Round 10: S = QK^T uses FP16 accumulators (m16n8k16.f16 — 2x rate if the
// legacy-HMMA fp32-accum half-rate hypothesis holds). PV stays fp32 accum.
// ---------------------------------------------------------------------------
__global__ __launch_bounds__(128, 4) void flash_attn(float* __restrict__ out) {
    const int bh = blockIdx.y;
    const int b = bh >> 4, h = bh & 15;
    const int q0 = blockIdx.x * 64;

    __shared__ __align__(16) __half sQ[64 * 72];
    __shared__ __align__(16) __half sK[2][64 * 72];
    __shared__ __align__(16) __half sV[2][64 * 72];
    __shared__ __align__(16) float sMask[2][64];

    const int tid = threadIdx.x, lane = tid & 31, warp = tid >> 5;
    const int g = lane >> 2, t4 = lane & 3;
    const __half* Q = g_q + (size_t)bh * SEQ * HD;
    const __half* K = g_k + (size_t)bh * SEQ * HD;
    const __half* V = g_v + (size_t)bh * SEQ * HD;
    const float* maskRow = g_maskl2 + (size_t)b * SEQ;

    auto prefetch = [&](int tile, int buf) {
        const __half* Kt = K + (size_t)tile * 64 * HD;
        const __half* Vt = V + (size_t)tile * 64 * HD;
#pragma unroll
        for (int t = 0; t < 4; t++) {
            int cix = tid + t * 128;
            int row = cix >> 3, seg = cix & 7;
            cp_async16(smem_u32(&sK[buf][row * 72 + seg * 8]), &Kt[row * 64 + seg * 8]);
            cp_async16(smem_u32(&sV[buf][row * 72 + seg * 8]), &Vt[row * 64 + seg * 8]);
        }
        if (tid < 16)
            cp_async16(smem_u32(&sMask[buf][tid * 4]), &maskRow[tile * 64 + tid * 4]);
        cp_commit();
    };

    prefetch(0, 0);

    for (int i = tid; i < 64 * 8; i += 128) {
        int row = i >> 3, seg = i & 7;
        *(uint4*)&sQ[row * 72 + seg * 8] =
            *(const uint4*)&Q[(size_t)(q0 + row) * HD + seg * 8];
    }
    __syncthreads();

    const int wr0 = warp * 16;
    uint32_t aq[4][4];
#pragma unroll
    for (int kk = 0; kk < 4; kk++) {
        int row = wr0 + (lane & 15);
        int col = kk * 16 + (lane >> 4) * 8;
        ldmatrix_x4(aq[kk][0], aq[kk][1], aq[kk][2], aq[kk][3],
                    smem_u32(&sQ[row * 72 + col]));
    }

    float o[8][4];
#pragma unroll
    for (int j = 0; j < 8; j++)
#pragma unroll
        for (int e = 0; e < 4; e++) o[j][e] = 0.f;
    float mrow[2] = {-1e30f, -1e30f};   // log2-domain running max
    float lp[2] = {0.f, 0.f};           // per-lane partial denominators
    const float scale2 = 0.125f * LOG2E;  // fold log2e into the QK scale

    const int NT = SEQ / 64;
    for (int it0 = 0; it0 < NT; it0 += 2) {
#pragma unroll
        for (int u = 0; u < 2; u++) {
            const int it = it0 + u;
            if (it + 1 < NT) {
                prefetch(it + 1, u ^ 1);
                cp_wait1();
            } else {
                cp_wait0();
            }
            __syncthreads();

            const __half* tK = sK[u];
            const __half* tV = sV[u];
            const float* tM = sMask[u];

            // ---- S = Q K^T (fp16 accumulate, K depth 64) ----
            uint32_t s16[8][2];
#pragma unroll
            for (int j = 0; j < 8; j++) { s16[j][0] = 0u; s16[j][1] = 0u; }

#pragma unroll
            for (int kk = 0; kk < 4; kk++) {
                uint32_t bk[8][2];
#pragma unroll
                for (int jb = 0; jb < 4; jb++) {
                    int row = jb * 16 + (lane & 7) + ((lane >= 16) ? 8 : 0);
                    int col = kk * 16 + ((lane >> 3) & 1) * 8;
                    uint32_t r0, r1, r2, r3;
                    ldmatrix_x4(r0, r1, r2, r3, smem_u32(&tK[row * 72 + col]));
                    bk[jb * 2][0] = r0; bk[jb * 2][1] = r1;
                    bk[jb * 2 + 1][0] = r2; bk[jb * 2 + 1][1] = r3;
                }
#pragma unroll
                for (int j = 0; j < 8; j++) mma16816_f16(s16[j], aq[kk], bk[j]);
            }

            // unpack to fp32, scale + mask (log2 domain)
            float sc[8][4];
#pragma unroll
            for (int j = 0; j < 8; j++) {
                float2 s01 = __half22float2(*(__half2*)&s16[j][0]);
                float2 s23 = __half22float2(*(__half2*)&s16[j][1]);
                float2 mk = *(const float2*)&tM[j * 8 + t4 * 2];
                sc[j][0] = s01.x * scale2 + mk.x;
                sc[j][1] = s01.y * scale2 + mk.y;
                sc[j][2] = s23.x * scale2 + mk.x;
                sc[j][3] = s23.y * scale2 + mk.y;
            }

            // ---- online softmax (base-2) ----
            float tmax0 = -1e30f, tmax1 = -1e30f;
#pragma unroll
            for (int j = 0; j < 8; j++) {
                tmax0 = fmaxf(tmax0, fmaxf(sc[j][0], sc[j][1]));
                tmax1 = fmaxf(tmax1, fmaxf(sc[j][2], sc[j][3]));
            }
            tmax0 = fmaxf(tmax0, __shfl_xor_sync(0xffffffffu, tmax0, 1));
            tmax0 = fmaxf(tmax0, __shfl_xor_sync(0xffffffffu, tmax0, 2));
            tmax1 = fmaxf(tmax1, __shfl_xor_sync(0xffffffffu, tmax1, 1));
            tmax1 = fmaxf(tmax1, __shfl_xor_sync(0xffffffffu, tmax1, 2));

            float mnew0 = fmaxf(mrow[0], tmax0), mnew1 = fmaxf(mrow[1], tmax1);
            float alpha0 = exp2f(mrow[0] - mnew0), alpha1 = exp2f(mrow[1] - mnew1);
            mrow[0] = mnew0; mrow[1] = mnew1;

            // P = 2^(sc - m): pack fp32 diffs to half2, one EX2 per pair
            uint32_t ph[8][2];
            uint32_t racc0 = 0, racc1 = 0;
#pragma unroll
            for (int j = 0; j < 8; j++) {
                uint32_t p01 = ex2_h2(pack_half2(sc[j][0] - mnew0, sc[j][1] - mnew0));
                uint32_t p23 = ex2_h2(pack_half2(sc[j][2] - mnew1, sc[j][3] - mnew1));
                ph[j][0] = p01; ph[j][1] = p23;
                racc0 = hadd2u(racc0, p01);
                racc1 = hadd2u(racc1, p23);
            }
            float2 r0 = __half22float2(*(__half2*)&racc0);
            float2 r1 = __half22float2(*(__half2*)&racc1);
            lp[0] = lp[0] * alpha0 + (r0.x + r0.y);
            lp[1] = lp[1] * alpha1 + (r1.x + r1.y);

#pragma unroll
            for (int j = 0; j < 8; j++) {
                o[j][0] *= alpha0; o[j][1] *= alpha0;
                o[j][2] *= alpha1; o[j][3] *= alpha1;
            }

            // ---- O += P V (fp32 accumulate) ----
#pragma unroll
            for (int kk = 0; kk < 4; kk++) {
                uint32_t ap[4] = {ph[2 * kk][0], ph[2 * kk][1],
                                  ph[2 * kk + 1][0], ph[2 * kk + 1][1]};
                uint32_t bv[8][2];
#pragma unroll
                for (int jb = 0; jb < 4; jb++) {
                    int row = kk * 16 + (lane & 7) + ((lane >> 3) & 1) * 8;
                    int col = jb * 16 + ((lane >= 16) ? 8 : 0);
                    uint32_t r2, r3, r4, r5;
                    ldmatrix_x4_trans(r2, r3, r4, r5, smem_u32(&tV[row * 72 + col]));
                    bv[jb * 2][0] = r2; bv[jb * 2][1] = r3;
                    bv[jb * 2 + 1][0] = r4; bv[jb * 2 + 1][1] = r5;
                }
#pragma unroll
                for (int j = 0; j < 8; j++) mma16816(o[j], ap, bv[j]);
            }
            __syncthreads();
        }
    }

    // ---- epilogue: lane-reduce denominators, normalize, store ----
    float l0 = lp[0], l1 = lp[1];
    l0 += __shfl_xor_sync(0xffffffffu, l0, 1);
    l0 += __shfl_xor_sync(0xffffffffu, l0, 2);
    l1 += __shfl_xor_sync(0xffffffffu, l1, 1);
    l1 += __shfl_xor_sync(0xffffffffu, l1, 2);
    float inv0 = 1.f / l0, inv1 = 1.f / l1;
#pragma unroll
    for (int j = 0; j < 8; j++) {
        int row0 = q0 + wr0 + g;
        int col = j * 8 + t4 * 2;
        size_t base0 = ((size_t)(b * SEQ + row0)) * HID + h * 64 + col;
        size_t base1 = ((size_t)(b * SEQ + row0 + 8)) * HID + h * 64 + col;
        *(float2*)&out[base0] = make_float2(o[j][0] * inv0, o[j][1] * inv0);
        *(float2*)&out[base1] = make_float2(o[j][2] * inv1, o[j][3] * inv1);
    }
}

// ---------------------------------------------------------------------------
extern "C" void kernel_launch(void* const* d_in, const int* in_sizes, int n_in,
                              void* d_out, int out_size) {
    const float* former = (const float*)d_in[0];
    const float* latter = (const float*)d_in[1];
    const float* mask   = (const float*)d_in[2];
    const float* Wq = (const float*)d_in[3];
    const float* bq = (const float*)d_in[4];
    const float* Wk = (const float*)d_in[5];
    const float* bk = (const float*)d_in[6];
    const float* Wv = (const float*)d_in[7];
    const float* bv = (const float*)d_in[8];

    size_t cvt_blocks = (CVT_TOTAL / 4 + 255) / 256;
    convert_inputs<<<(unsigned)cvt_blocks, 256>>>(former, latter, Wq, Wk, Wv);
    scale_mask<<<(NB * SEQ + 255) / 256, 256>>>(mask);

    dim3 g1(HID / 128, (NB * SEQ) / 128, 3);
    qkv_gemm<<<g1, 256>>>(bq, bk, bv);

    dim3 g2(SEQ / 64, NB * NH);
    flash_attn<<<g2, 128>>>((float*)d_out);
}

// round 11
// speedup vs baseline: 1.0420x; 1.0167x over previous
#include <cuda_runtime.h>
#include <cuda_fp16.h>
#include <cstdint>

#define NB 2
#define NH 16
#define HD 64
#define SEQ 2048
#define HID 1024

// fp16 scratch: Q/K/V in [b, h, s, d] layout (8 MB each, static => allocation-free)
__device__ __half g_q[(size_t)NB * NH * SEQ * HD];
__device__ __half g_k[(size_t)NB * NH * SEQ * HD];
__device__ __half g_v[(size_t)NB * NH * SEQ * HD];

// fp16 copies of inputs: former[4M] | latter[4M] | Wq[1M] | Wk[1M] | Wv[1M]
#define CVT_FORMER 0
#define CVT_LATTER ((size_t)NB * SEQ * HID)
#define CVT_W      ((size_t)2 * NB * SEQ * HID)
#define CVT_TOTAL  (CVT_W + (size_t)3 * HID * HID)
__device__ __half g_cvt[CVT_TOTAL];

// mask pre-scaled by log2(e), stored fp16 (log2-domain softmax)
__device__ __half g_maskl2h[(size_t)NB * SEQ];

#define LOG2E 1.44269504088896340736f

// ---------------------------------------------------------------------------
// PTX helpers
// ---------------------------------------------------------------------------
__device__ __forceinline__ uint32_t smem_u32(const void* p) {
    return (uint32_t)__cvta_generic_to_shared(p);
}

__device__ __forceinline__ void ldmatrix_x4(uint32_t& r0, uint32_t& r1, uint32_t& r2,
                                            uint32_t& r3, uint32_t addr) {
    asm volatile("ldmatrix.sync.aligned.m8n8.x4.shared.b16 {%0,%1,%2,%3},[%4];\n"
                 : "=r"(r0), "=r"(r1), "=r"(r2), "=r"(r3) : "r"(addr));
}

__device__ __forceinline__ void ldmatrix_x4_trans(uint32_t& r0, uint32_t& r1, uint32_t& r2,
                                                  uint32_t& r3, uint32_t addr) {
    asm volatile("ldmatrix.sync.aligned.m8n8.x4.trans.shared.b16 {%0,%1,%2,%3},[%4];\n"
                 : "=r"(r0), "=r"(r1), "=r"(r2), "=r"(r3) : "r"(addr));
}

// fp32-accumulate mma (GEMM + PV)
__device__ __forceinline__ void mma16816(float* c, const uint32_t* a, const uint32_t* b) {
    asm volatile(
        "mma.sync.aligned.m16n8k16.row.col.f32.f16.f16.f32 "
        "{%0,%1,%2,%3},{%4,%5,%6,%7},{%8,%9},{%0,%1,%2,%3};\n"
        : "+f"(c[0]), "+f"(c[1]), "+f"(c[2]), "+f"(c[3])
        : "r"(a[0]), "r"(a[1]), "r"(a[2]), "r"(a[3]), "r"(b[0]), "r"(b[1]));
}

// fp16-accumulate mma (flash S = QK^T; K depth only 64 so fp16 accum is safe)
__device__ __forceinline__ void mma16816_f16(uint32_t* d, const uint32_t* a,
                                             const uint32_t* b) {
    asm volatile(
        "mma.sync.aligned.m16n8k16.row.col.f16.f16.f16.f16 "
        "{%0,%1},{%2,%3,%4,%5},{%6,%7},{%0,%1};\n"
        : "+r"(d[0]), "+r"(d[1])
        : "r"(a[0]), "r"(a[1]), "r"(a[2]), "r"(a[3]), "r"(b[0]), "r"(b[1]));
}

__device__ __forceinline__ uint32_t pack_half2(float x, float y) {
    __half2 h = __floats2half2_rn(x, y);
    return *(uint32_t*)&h;
}

__device__ __forceinline__ uint32_t ex2_h2(uint32_t x) {
    uint32_t r;
    asm("ex2.approx.f16x2 %0, %1;" : "=r"(r) : "r"(x));
    return r;
}
__device__ __forceinline__ uint32_t hadd2u(uint32_t a, uint32_t b) {
    uint32_t r;
    asm("add.f16x2 %0, %1, %2;" : "=r"(r) : "r"(a), "r"(b));
    return r;
}
__device__ __forceinline__ uint32_t hsub2u(uint32_t a, uint32_t b) {
    uint32_t r;
    asm("sub.f16x2 %0, %1, %2;" : "=r"(r) : "r"(a), "r"(b));
    return r;
}
__device__ __forceinline__ uint32_t hmax2u(uint32_t a, uint32_t b) {
    uint32_t r;
    asm("max.f16x2 %0, %1, %2;" : "=r"(r) : "r"(a), "r"(b));
    return r;
}
__device__ __forceinline__ uint32_t hfma2u(uint32_t a, uint32_t b, uint32_t c) {
    uint32_t r;
    asm("fma.rn.f16x2 %0, %1, %2, %3;" : "=r"(r) : "r"(a), "r"(b), "r"(c));
    return r;
}

__device__ __forceinline__ void cp_async16(uint32_t dst, const void* src) {
    asm volatile("cp.async.cg.shared.global [%0], [%1], 16;\n" ::"r"(dst), "l"(src));
}
__device__ __forceinline__ void cp_commit() {
    asm volatile("cp.async.commit_group;\n" ::: "memory");
}
__device__ __forceinline__ void cp_wait1() {
    asm volatile("cp.async.wait_group 1;\n" ::: "memory");
}
__device__ __forceinline__ void cp_wait0() {
    asm volatile("cp.async.wait_group 0;\n" ::: "memory");
}

// XOR swizzle for 64-half (128B) rows: 16B chunk index ^= row%8.
// Conflict-free for ldmatrix (rows r..r+7 hit distinct 16B groups).
__device__ __forceinline__ uint32_t swz(int row, int colHalf) {
    return (uint32_t)(row * 128 + ((((colHalf >> 3) ^ row) & 7) << 4) +
                      ((colHalf & 7) << 1));
}

// ---------------------------------------------------------------------------
// Convert kernel: fp32 inputs -> fp16 staging (memory-bound, ~12 us)
// ---------------------------------------------------------------------------
__global__ __launch_bounds__(256) void convert_inputs(
    const float* __restrict__ former, const float* __restrict__ latter,
    const float* __restrict__ Wq, const float* __restrict__ Wk,
    const float* __restrict__ Wv) {
    size_t i4 = ((size_t)blockIdx.x * 256 + threadIdx.x) * 4;
    if (i4 >= CVT_TOTAL) return;

    const float* src;
    size_t off;
    if (i4 < CVT_LATTER)      { src = former; off = i4; }
    else if (i4 < CVT_W)      { src = latter; off = i4 - CVT_LATTER; }
    else {
        size_t w = i4 - CVT_W;
        size_t wsz = (size_t)HID * HID;
        if (w < wsz)            { src = Wq; off = w; }
        else if (w < 2 * wsz)   { src = Wk; off = w - wsz; }
        else                    { src = Wv; off = w - 2 * wsz; }
    }
    float4 v = *(const float4*)&src[off];
    __half2* dst = (__half2*)&g_cvt[i4];
    dst[0] = __floats2half2_rn(v.x, v.y);
    dst[1] = __floats2half2_rn(v.z, v.w);
}

// mask * log2e -> fp16  (4096 elements)
__global__ __launch_bounds__(256) void scale_mask(const float* __restrict__ mask) {
    int i = blockIdx.x * 256 + threadIdx.x;
    if (i < NB * SEQ) g_maskl2h[i] = __float2half(mask[i] * LOG2E);
}

// ---------------------------------------------------------------------------
// QKV projection GEMM (fp16 in, fp32 accum): Y = X @ W + b, out fp16 [b,h,s,d].
// 2-stage cp.async double buffering. (proven config — ~104 us; fp32 accum
// REQUIRED: K=1024 makes fp16 accum error ~1e-2)
// ---------------------------------------------------------------------------
__global__ __launch_bounds__(256) void qkv_gemm(
    const float* __restrict__ bq, const float* __restrict__ bk,
    const float* __restrict__ bv) {
    const int which = blockIdx.z;
    const __half* X    = g_cvt + ((which == 0) ? CVT_FORMER : CVT_LATTER);
    const __half* W    = g_cvt + CVT_W + (size_t)which * HID * HID;
    const float* bias  = (which == 0) ? bq : (which == 1) ? bk : bv;
    __half* out        = (which == 0) ? g_q : (which == 1) ? g_k : g_v;

    __shared__ __align__(16) __half sA[2][128 * 40];
    __shared__ __align__(16) __half sB[2][32 * 136];

    const int tid = threadIdx.x;
    const int lane = tid & 31, warp = tid >> 5;
    const int wm = warp >> 2, wn = warp & 3;
    const int m0 = blockIdx.y * 128, n0 = blockIdx.x * 128;

    auto prefetch = [&](int kb, int buf) {
#pragma unroll
        for (int t = 0; t < 2; t++) {
            int i = tid + t * 256;
            int row = i >> 2, seg = i & 3;
            cp_async16(smem_u32(&sA[buf][row * 40 + seg * 8]),
                       &X[(size_t)(m0 + row) * HID + kb + seg * 8]);
        }
#pragma unroll
        for (int t = 0; t < 2; t++) {
            int i = tid + t * 256;
            int row = i >> 4, seg = i & 15;
            cp_async16(smem_u32(&sB[buf][row * 136 + seg * 8]),
                       &W[(size_t)(kb + row) * HID + n0 + seg * 8]);
        }
        cp_commit();
    };

    float c[4][4][4];
#pragma unroll
    for (int i = 0; i < 4; i++)
#pragma unroll
        for (int j = 0; j < 4; j++)
#pragma unroll
            for (int e = 0; e < 4; e++) c[i][j][e] = 0.f;

    prefetch(0, 0);

    const int NKB = HID / 32;
    for (int it = 0; it < NKB; it++) {
        const int cur = it & 1;
        if (it + 1 < NKB) {
            prefetch((it + 1) * 32, cur ^ 1);
            cp_wait1();
        } else {
            cp_wait0();
        }
        __syncthreads();

        const __half* tA = sA[cur];
        const __half* tB = sB[cur];

#pragma unroll
        for (int ks = 0; ks < 2; ks++) {
            const int k0 = ks * 16;
            uint32_t a[4][4];
#pragma unroll
            for (int im = 0; im < 4; im++) {
                int row = wm * 64 + im * 16 + (lane & 15);
                int col = k0 + (lane >> 4) * 8;
                ldmatrix_x4(a[im][0], a[im][1], a[im][2], a[im][3],
                            smem_u32(&tA[row * 40 + col]));
            }
            uint32_t bf[4][2];
#pragma unroll
            for (int jb = 0; jb < 2; jb++) {
                int nn = wn * 32 + jb * 16 + ((lane >= 16) ? 8 : 0);
                int kr = k0 + (lane & 7) + ((lane >> 3) & 1) * 8;
                uint32_t r0, r1, r2, r3;
                ldmatrix_x4_trans(r0, r1, r2, r3, smem_u32(&tB[kr * 136 + nn]));
                bf[jb * 2][0] = r0; bf[jb * 2][1] = r1;
                bf[jb * 2 + 1][0] = r2; bf[jb * 2 + 1][1] = r3;
            }
#pragma unroll
            for (int im = 0; im < 4; im++)
#pragma unroll
                for (int jn = 0; jn < 4; jn++) mma16816(c[im][jn], a[im], bf[jn]);
        }
        __syncthreads();
    }

    const int g = lane >> 2, t4 = lane & 3;
#pragma unroll
    for (int im = 0; im < 4; im++) {
#pragma unroll
        for (int jn = 0; jn < 4; jn++) {
            int row0 = m0 + wm * 64 + im * 16 + g;
            int col = n0 + wn * 32 + jn * 8 + t4 * 2;
            float b0 = bias[col], b1 = bias[col + 1];
            int bb = row0 >> 11;
            int ss = row0 & (SEQ - 1);
            int hh = col >> 6, dd = col & 63;
            size_t base = ((size_t)(bb * NH + hh) * SEQ);
            *(__half2*)&out[(base + ss) * HD + dd] =
                __floats2half2_rn(c[im][jn][0] + b0, c[im][jn][1] + b1);
            *(__half2*)&out[(base + ((row0 + 8) & (SEQ - 1))) * HD + dd] =
                __floats2half2_rn(c[im][jn][2] + b0, c[im][jn][3] + b1);
        }
    }
}

// ---------------------------------------------------------------------------
// Flash attention: 1 CTA per (bh, 64-row Q tile). 4 warps x 16 rows.
// Round 11: XOR-swizzled smem (40.5 KB total) + full fp16-domain softmax
// (HFMA2/HMAX2/HSUB2/EX2.f16x2) => 5 CTAs/SM occupancy target.
// ---------------------------------------------------------------------------
__global__ __launch_bounds__(128, 5) void flash_attn(float* __restrict__ out) {
    const int bh = blockIdx.y;
    const int b = bh >> 4, h = bh & 15;
    const int q0 = blockIdx.x * 64;

    __shared__ __align__(128) __half sQ[64 * 64];
    __shared__ __align__(128) __half sK[2][64 * 64];
    __shared__ __align__(128) __half sV[2][64 * 64];
    __shared__ __align__(8) __half sMask[2][64];

    const int tid = threadIdx.x, lane = tid & 31, warp = tid >> 5;
    const int g = lane >> 2, t4 = lane & 3;
    const __half* Q = g_q + (size_t)bh * SEQ * HD;
    const __half* K = g_k + (size_t)bh * SEQ * HD;
    const __half* V = g_v + (size_t)bh * SEQ * HD;
    const __half* maskRow = g_maskl2h + (size_t)b * SEQ;

    const uint32_t sKb0 = smem_u32(sK[0]), sKb1 = smem_u32(sK[1]);
    const uint32_t sVb0 = smem_u32(sV[0]), sVb1 = smem_u32(sV[1]);

    auto prefetch = [&](int tile, int buf) {
        const __half* Kt = K + (size_t)tile * 64 * HD;
        const __half* Vt = V + (size_t)tile * 64 * HD;
        const uint32_t kb = buf ? sKb1 : sKb0;
        const uint32_t vb = buf ? sVb1 : sVb0;
#pragma unroll
        for (int t = 0; t < 4; t++) {
            int cix = tid + t * 128;
            int row = cix >> 3, seg = cix & 7;
            uint32_t off = (uint32_t)(row * 128 + (((seg ^ row) & 7) << 4));
            cp_async16(kb + off, &Kt[row * 64 + seg * 8]);
            cp_async16(vb + off, &Vt[row * 64 + seg * 8]);
        }
        if (tid < 8)
            cp_async16(smem_u32(&sMask[buf][tid * 8]), &maskRow[tile * 64 + tid * 8]);
        cp_commit();
    };

    prefetch(0, 0);

    {
        const uint32_t qb = smem_u32(sQ);
        for (int i = tid; i < 64 * 8; i += 128) {
            int row = i >> 3, seg = i & 7;
            uint32_t off = (uint32_t)(row * 128 + (((seg ^ row) & 7) << 4));
            asm volatile("cp.async.cg.shared.global [%0], [%1], 16;\n" ::"r"(qb + off),
                         "l"(&Q[(size_t)(q0 + row) * HD + seg * 8]));
        }
        cp_commit();
    }
    cp_wait0();
    __syncthreads();

    const int wr0 = warp * 16;
    uint32_t aq[4][4];
#pragma unroll
    for (int kk = 0; kk < 4; kk++) {
        int row = wr0 + (lane & 15);
        int col = kk * 16 + (lane >> 4) * 8;
        ldmatrix_x4(aq[kk][0], aq[kk][1], aq[kk][2], aq[kk][3],
                    smem_u32(sQ) + swz(row, col));
    }
    // re-issue tile-0 prefetch consumed ordering: tile 0 already loaded above
    // (group was committed before Q; cp_wait0 above drained BOTH groups).

    float o[8][4];
#pragma unroll
    for (int j = 0; j < 8; j++)
#pragma unroll
        for (int e = 0; e < 4; e++) o[j][e] = 0.f;
    uint32_t mrow_h2 = 0xFC00FC00u;     // (-inf, -inf) packed half2
    float lp[2] = {0.f, 0.f};
    const uint32_t scaleh2 = pack_half2(0.125f * LOG2E, 0.125f * LOG2E);

    const int NT = SEQ / 64;
    for (int it0 = 0; it0 < NT; it0 += 2) {
#pragma unroll
        for (int u = 0; u < 2; u++) {
            const int it = it0 + u;
            if (it + 1 < NT) {
                prefetch(it + 1, u ^ 1);
                cp_wait1();
            } else {
                cp_wait0();
            }
            __syncthreads();

            const uint32_t kb = u ? sKb1 : sKb0;
            const uint32_t vb = u ? sVb1 : sVb0;
            const __half* tM = sMask[u];

            // ---- S = Q K^T (fp16 accumulate) ----
            uint32_t s16[8][2];
#pragma unroll
            for (int j = 0; j < 8; j++) { s16[j][0] = 0u; s16[j][1] = 0u; }

#pragma unroll
            for (int kk = 0; kk < 4; kk++) {
                uint32_t bk[8][2];
#pragma unroll
                for (int jb = 0; jb < 4; jb++) {
                    int row = jb * 16 + (lane & 7) + ((lane >= 16) ? 8 : 0);
                    int col = kk * 16 + ((lane >> 3) & 1) * 8;
                    uint32_t r0, r1, r2, r3;
                    ldmatrix_x4(r0, r1, r2, r3, kb + swz(row, col));
                    bk[jb * 2][0] = r0; bk[jb * 2][1] = r1;
                    bk[jb * 2 + 1][0] = r2; bk[jb * 2 + 1][1] = r3;
                }
#pragma unroll
                for (int j = 0; j < 8; j++) mma16816_f16(s16[j], aq[kk], bk[j]);
            }

            // ---- fp16-domain softmax (log2) ----
            // scale + mask
#pragma unroll
            for (int j = 0; j < 8; j++) {
                uint32_t mk = *(const uint32_t*)&tM[j * 8 + t4 * 2];
                s16[j][0] = hfma2u(s16[j][0], scaleh2, mk);
                s16[j][1] = hfma2u(s16[j][1], scaleh2, mk);
            }
            // row max (s16[j][0] = row g, s16[j][1] = row g+8)
            uint32_t vm0 = s16[0][0], vm1 = s16[0][1];
#pragma unroll
            for (int j = 1; j < 8; j++) {
                vm0 = hmax2u(vm0, s16[j][0]);
                vm1 = hmax2u(vm1, s16[j][1]);
            }
            vm0 = hmax2u(vm0, __byte_perm(vm0, vm0, 0x1032));
            vm1 = hmax2u(vm1, __byte_perm(vm1, vm1, 0x1032));
            vm0 = hmax2u(vm0, __shfl_xor_sync(0xffffffffu, vm0, 1));
            vm0 = hmax2u(vm0, __shfl_xor_sync(0xffffffffu, vm0, 2));
            vm1 = hmax2u(vm1, __shfl_xor_sync(0xffffffffu, vm1, 1));
            vm1 = hmax2u(vm1, __shfl_xor_sync(0xffffffffu, vm1, 2));
            uint32_t tmax_h2 = __byte_perm(vm0, vm1, 0x5410);  // (maxg, maxg8)

            uint32_t mnew_h2 = hmax2u(mrow_h2, tmax_h2);
            uint32_t alpha_h2 = ex2_h2(hsub2u(mrow_h2, mnew_h2));
            mrow_h2 = mnew_h2;
            float2 af = __half22float2(*(__half2*)&alpha_h2);

            uint32_t mn0 = __byte_perm(mnew_h2, mnew_h2, 0x1010);  // splat row-g max
            uint32_t mn1 = __byte_perm(mnew_h2, mnew_h2, 0x3232);  // splat row-g8 max

            uint32_t racc0 = 0, racc1 = 0;
#pragma unroll
            for (int j = 0; j < 8; j++) {
                s16[j][0] = ex2_h2(hsub2u(s16[j][0], mn0));
                s16[j][1] = ex2_h2(hsub2u(s16[j][1], mn1));
                racc0 = hadd2u(racc0, s16[j][0]);
                racc1 = hadd2u(racc1, s16[j][1]);
            }
            float2 r0 = __half22float2(*(__half2*)&racc0);
            float2 r1 = __half22float2(*(__half2*)&racc1);
            lp[0] = lp[0] * af.x + (r0.x + r0.y);
            lp[1] = lp[1] * af.y + (r1.x + r1.y);

#pragma unroll
            for (int j = 0; j < 8; j++) {
                o[j][0] *= af.x; o[j][1] *= af.x;
                o[j][2] *= af.y; o[j][3] *= af.y;
            }

            // ---- O += P V (fp32 accumulate); P fragments = s16 ----
#pragma unroll
            for (int kk = 0; kk < 4; kk++) {
                uint32_t ap[4] = {s16[2 * kk][0], s16[2 * kk][1],
                                  s16[2 * kk + 1][0], s16[2 * kk + 1][1]};
                uint32_t bv[8][2];
#pragma unroll
                for (int jb = 0; jb < 4; jb++) {
                    int row = kk * 16 + (lane & 7) + ((lane >> 3) & 1) * 8;
                    int col = jb * 16 + ((lane >= 16) ? 8 : 0);
                    uint32_t r2, r3, r4, r5;
                    ldmatrix_x4_trans(r2, r3, r4, r5, vb + swz(row, col));
                    bv[jb * 2][0] = r2; bv[jb * 2][1] = r3;
                    bv[jb * 2 + 1][0] = r4; bv[jb * 2 + 1][1] = r5;
                }
#pragma unroll
                for (int j = 0; j < 8; j++) mma16816(o[j], ap, bv[j]);
            }
            __syncthreads();
        }
    }

    // ---- epilogue: lane-reduce denominators, normalize, store ----
    float l0 = lp[0], l1 = lp[1];
    l0 += __shfl_xor_sync(0xffffffffu, l0, 1);
    l0 += __shfl_xor_sync(0xffffffffu, l0, 2);
    l1 += __shfl_xor_sync(0xffffffffu, l1, 1);
    l1 += __shfl_xor_sync(0xffffffffu, l1, 2);
    float inv0 = 1.f / l0, inv1 = 1.f / l1;
#pragma unroll
    for (int j = 0; j < 8; j++) {
        int row0 = q0 + wr0 + g;
        int col = j * 8 + t4 * 2;
        size_t base0 = ((size_t)(b * SEQ + row0)) * HID + h * 64 + col;
        size_t base1 = ((size_t)(b * SEQ + row0 + 8)) * HID + h * 64 + col;
        *(float2*)&out[base0] = make_float2(o[j][0] * inv0, o[j][1] * inv0);
        *(float2*)&out[base1] = make_float2(o[j][2] * inv1, o[j][3] * inv1);
    }
}

// ---------------------------------------------------------------------------
extern "C" void kernel_launch(void* const* d_in, const int* in_sizes, int n_in,
                              void* d_out, int out_size) {
    const float* former = (const float*)d_in[0];
    const float* latter = (const float*)d_in[1];
    const float* mask   = (const float*)d_in[2];
    const float* Wq = (const float*)d_in[3];
    const float* bq = (const float*)d_in[4];
    const float* Wk = (const float*)d_in[5];
    const float* bk = (const float*)d_in[6];
    const float* Wv = (const float*)d_in[7];
    const float* bv = (const float*)d_in[8];

    size_t cvt_blocks = (CVT_TOTAL / 4 + 255) / 256;
    convert_inputs<<<(unsigned)cvt_blocks, 256>>>(former, latter, Wq, Wk, Wv);
    scale_mask<<<(NB * SEQ + 255) / 256, 256>>>(mask);

    dim3 g1(HID / 128, (NB * SEQ) / 128, 3);
    qkv_gemm<<<g1, 256>>>(bq, bk, bv);

    dim3 g2(SEQ / 64, NB * NH);
    flash_attn<<<g2, 128>>>((float*)d_out);
}